// round 1
// baseline (speedup 1.0000x reference)
#include <cuda_runtime.h>
#include <math.h>

#define NN      2048
#define GG      32
#define NPG     64
#define EE      16384
#define EPG     512
#define HID     256
#define NH      8
#define HD      32
#define EF      16
#define SCALE_F 0.17677669529663687f   // 1/sqrt(32)

// ---------------- scratch (device globals, no runtime allocation) ----------
__device__ float g_q[NN * HID];
__device__ float g_k[NN * HID];
__device__ float g_v[NN * HID];
__device__ float g_attn[NN * HID];

// ---------------------------------------------------------------------------
// Generic 64x64 output-tile GEMM:  C[row0:row0+64, col0:col0+64] =
//     A[M,256] @ B[256,256] + bias[256]    (all row-major, ld = 256)
// 256 threads, each computes a 4x4 micro-tile. K-loop step 16.
// ---------------------------------------------------------------------------
__device__ __forceinline__ void gemm_tile_64x64(
    const float* __restrict__ A,
    const float* __restrict__ B,
    const float* __restrict__ bias,
    float* __restrict__ C,
    int row0, int col0)
{
    __shared__ float As[16][64];      // [k][m]
    __shared__ float Bs[16][68];      // [k][n], padded (272B rows, 16B aligned)

    const int tid = threadIdx.x;      // 0..255
    const int tx  = tid & 15;         // 0..15  -> col group
    const int ty  = tid >> 4;         // 0..15  -> row group

    float acc[4][4];
#pragma unroll
    for (int i = 0; i < 4; i++)
#pragma unroll
        for (int j = 0; j < 4; j++) acc[i][j] = 0.f;

    for (int k0 = 0; k0 < 256; k0 += 16) {
        // --- load A tile: 64 rows x 16 k ---
        {
            const int m  = tid >> 2;          // 0..63
            const int kq = tid & 3;           // 0..3 (quad of 4 k)
            float4 a = *(const float4*)&A[(row0 + m) * 256 + k0 + kq * 4];
            As[kq * 4 + 0][m] = a.x;
            As[kq * 4 + 1][m] = a.y;
            As[kq * 4 + 2][m] = a.z;
            As[kq * 4 + 3][m] = a.w;
        }
        // --- load B tile: 16 k x 64 n ---
        {
            const int kk = tid >> 4;          // 0..15
            const int n4 = (tid & 15) * 4;    // 0..60
            float4 b = *(const float4*)&B[(k0 + kk) * 256 + col0 + n4];
            *(float4*)&Bs[kk][n4] = b;
        }
        __syncthreads();

#pragma unroll
        for (int kk = 0; kk < 16; kk++) {
            float4 av = *(const float4*)&As[kk][ty * 4];
            float4 bv = *(const float4*)&Bs[kk][tx * 4];
            float a[4] = {av.x, av.y, av.z, av.w};
            float b[4] = {bv.x, bv.y, bv.z, bv.w};
#pragma unroll
            for (int i = 0; i < 4; i++)
#pragma unroll
                for (int j = 0; j < 4; j++)
                    acc[i][j] = fmaf(a[i], b[j], acc[i][j]);
        }
        __syncthreads();
    }

    // --- epilogue: add bias, store (vectorized, coalesced) ---
#pragma unroll
    for (int i = 0; i < 4; i++) {
        const int r = row0 + ty * 4 + i;
        const int c = col0 + tx * 4;
        float4 o;
        o.x = acc[i][0] + bias[c + 0];
        o.y = acc[i][1] + bias[c + 1];
        o.z = acc[i][2] + bias[c + 2];
        o.w = acc[i][3] + bias[c + 3];
        *(float4*)&C[r * 256 + c] = o;
    }
}

// ---------------------------------------------------------------------------
// K1: fused QKV projection. grid (32, 12): by/4 selects {Wq,Wk,Wv}.
// ---------------------------------------------------------------------------
__global__ void __launch_bounds__(256) qkv_kernel(
    const float* __restrict__ nodes,
    const float* __restrict__ Wq, const float* __restrict__ bq,
    const float* __restrict__ Wk, const float* __restrict__ bk,
    const float* __restrict__ Wv, const float* __restrict__ bv)
{
    const int by    = blockIdx.y;          // 0..11
    const int which = by >> 2;             // 0:q 1:k 2:v
    const int col0  = (by & 3) * 64;
    const float* B    = (which == 0) ? Wq : (which == 1) ? Wk : Wv;
    const float* bias = (which == 0) ? bq : (which == 1) ? bk : bv;
    float* C          = (which == 0) ? g_q : (which == 1) ? g_k : g_v;
    gemm_tile_64x64(nodes, B, bias, C, blockIdx.x * 64, col0);
}

// ---------------------------------------------------------------------------
// K3: output projection: d_out = g_attn @ Wo + bo. grid (32, 4).
// ---------------------------------------------------------------------------
__global__ void __launch_bounds__(256) out_kernel(
    const float* __restrict__ Wo, const float* __restrict__ bo,
    float* __restrict__ out)
{
    gemm_tile_64x64(g_attn, Wo, bo, out, blockIdx.x * 64, blockIdx.y * 64);
}

// ---------------------------------------------------------------------------
// K2: per-(graph, head) attention with in-block edge bias.
// grid = 256 blocks (g = bid>>3, h = bid&7), 128 threads.
// ---------------------------------------------------------------------------
__global__ void __launch_bounds__(128) attn_kernel(
    const int* __restrict__ senders,
    const int* __restrict__ receivers,
    const float* __restrict__ edges,
    const float* __restrict__ We,     // [16, 8] row-major
    const float* __restrict__ be)     // [8]
{
    const int g = blockIdx.x >> 3;
    const int h = blockIdx.x & 7;
    const int tid = threadIdx.x;      // 0..127

    __shared__ float qs[64][33];
    __shared__ float ks[64][33];
    __shared__ float vs[64][33];
    __shared__ float sc[64][65];
    __shared__ float eb[EPG];

    // ---- load q,k,v head tiles (64 x 32), coalesced ----
    for (int idx = tid; idx < 64 * 32; idx += 128) {
        const int r = idx >> 5;
        const int c = idx & 31;
        const int ga = (g * 64 + r) * 256 + h * 32 + c;
        qs[r][c] = g_q[ga];
        ks[r][c] = g_k[ga];
        vs[r][c] = g_v[ga];
    }

    // ---- edge bias for this graph+head: eb[e] = edges[e]·We[:,h] + be[h] ----
    for (int e = tid; e < EPG; e += 128) {
        const float* ef = &edges[(g * EPG + e) * EF];
        float s = be[h];
#pragma unroll
        for (int f = 0; f < EF; f++) s = fmaf(ef[f], We[f * NH + h], s);
        eb[e] = s;
    }
    __syncthreads();

    // ---- scores: 64x64, thread tile = 4 rows x 8 cols (16 x 8 threads) ----
    {
        const int i0 = (tid >> 3) * 4;   // 0..60
        const int j0 = (tid & 7) * 8;    // 0..56
        float acc[4][8];
#pragma unroll
        for (int i = 0; i < 4; i++)
#pragma unroll
            for (int j = 0; j < 8; j++) acc[i][j] = 0.f;

        for (int d = 0; d < 32; d++) {
            float a[4], b[8];
#pragma unroll
            for (int i = 0; i < 4; i++) a[i] = qs[i0 + i][d];
#pragma unroll
            for (int j = 0; j < 8; j++) b[j] = ks[j0 + j][d];
#pragma unroll
            for (int i = 0; i < 4; i++)
#pragma unroll
                for (int j = 0; j < 8; j++)
                    acc[i][j] = fmaf(a[i], b[j], acc[i][j]);
        }
#pragma unroll
        for (int i = 0; i < 4; i++)
#pragma unroll
            for (int j = 0; j < 8; j++)
                sc[i0 + i][j0 + j] = acc[i][j] * SCALE_F;
    }
    __syncthreads();

    // ---- scatter edge bias: sc[recv_local][send_local] += eb[e] ----
    // (unique (s,r) pairs within a graph -> no write conflicts)
    for (int e = tid; e < EPG; e += 128) {
        const int ge = g * EPG + e;
        const int s  = senders[ge]   - g * 64;
        const int r  = receivers[ge] - g * 64;
        sc[r][s] += eb[e];
    }
    __syncthreads();

    // ---- softmax over j (64 keys), one warp per row ----
    {
        const int warp = tid >> 5;
        const int lane = tid & 31;
        for (int i = warp; i < 64; i += 4) {
            float x0 = sc[i][lane];
            float x1 = sc[i][lane + 32];
            float m = fmaxf(x0, x1);
#pragma unroll
            for (int o = 16; o > 0; o >>= 1)
                m = fmaxf(m, __shfl_xor_sync(0xffffffffu, m, o));
            float e0 = expf(x0 - m);
            float e1 = expf(x1 - m);
            float s = e0 + e1;
#pragma unroll
            for (int o = 16; o > 0; o >>= 1)
                s += __shfl_xor_sync(0xffffffffu, s, o);
            const float inv = 1.f / s;
            sc[i][lane]      = e0 * inv;
            sc[i][lane + 32] = e1 * inv;
        }
    }
    __syncthreads();

    // ---- AV: out[i][d] = sum_j p[i][j] * v[j][d]; thread tile 4x4 ----
    {
        const int i0 = (tid >> 3) * 4;   // 0..60
        const int d0 = (tid & 7) * 4;    // 0..28
        float acc[4][4];
#pragma unroll
        for (int i = 0; i < 4; i++)
#pragma unroll
            for (int d = 0; d < 4; d++) acc[i][d] = 0.f;

        for (int j = 0; j < 64; j++) {
            float p[4], b[4];
#pragma unroll
            for (int i = 0; i < 4; i++) p[i] = sc[i0 + i][j];
#pragma unroll
            for (int d = 0; d < 4; d++) b[d] = vs[j][d0 + d];
#pragma unroll
            for (int i = 0; i < 4; i++)
#pragma unroll
                for (int d = 0; d < 4; d++)
                    acc[i][d] = fmaf(p[i], b[d], acc[i][d]);
        }
#pragma unroll
        for (int i = 0; i < 4; i++) {
            float4 o = {acc[i][0], acc[i][1], acc[i][2], acc[i][3]};
            *(float4*)&g_attn[(g * 64 + i0 + i) * 256 + h * 32 + d0] = o;
        }
    }
}

// ---------------------------------------------------------------------------
extern "C" void kernel_launch(void* const* d_in, const int* in_sizes, int n_in,
                              void* d_out, int out_size)
{
    const float* nodes     = (const float*)d_in[0];
    const float* edges     = (const float*)d_in[1];
    // d_in[2] = n_node (constant 64 per graph, unused)
    const int*   senders   = (const int*)d_in[3];
    const int*   receivers = (const int*)d_in[4];
    const float* Wq = (const float*)d_in[5];
    const float* bq = (const float*)d_in[6];
    const float* Wk = (const float*)d_in[7];
    const float* bk = (const float*)d_in[8];
    const float* Wv = (const float*)d_in[9];
    const float* bv = (const float*)d_in[10];
    const float* Wo = (const float*)d_in[11];
    const float* bo = (const float*)d_in[12];
    const float* We = (const float*)d_in[13];
    const float* be = (const float*)d_in[14];
    float* out = (float*)d_out;

    qkv_kernel<<<dim3(32, 12), 256>>>(nodes, Wq, bq, Wk, bk, Wv, bv);
    attn_kernel<<<GG * NH, 128>>>(senders, receivers, edges, We, be);
    out_kernel<<<dim3(32, 4), 256>>>(Wo, bo, out);
}

// round 5
// speedup vs baseline: 1.7541x; 1.7541x over previous
#include <cuda_runtime.h>
#include <cuda_fp16.h>
#include <mma.h>
#include <math.h>
#include <stdint.h>

using namespace nvcuda;

#define NN      2048
#define GG      32
#define NPG     64
#define EE      16384
#define EPG     512
#define HID     256
#define NH      8
#define HD      32
#define EF      16
#define SCALE_F 0.17677669529663687f   // 1/sqrt(32)

// ---------------- scratch (device globals, no runtime allocation) ----------
__device__ __align__(16) __half g_nodes16[NN * HID];
__device__ __align__(16) __half g_wT16[1024 * HID];   // rows 0-767: Wq|Wk|Wv cols, 768-1023: Wo cols (K contiguous)
__device__ __align__(16) __half g_attn16[NN * HID];
__device__ float g_q[NN * HID];
__device__ float g_k[NN * HID];
__device__ float g_v[NN * HID];

// Smem geometry for the HMMA GEMM
static constexpr int LDA_S  = 264;                    // halves, pad 8
static constexpr int A_SM_B = 64  * LDA_S * 2;        // 33792 B
static constexpr int B_SM_B = 128 * LDA_S * 2;        // 67584 B
static constexpr int SMEM_GEMM = A_SM_B + B_SM_B;     // 101376 B (dynamic)
static constexpr int LDC_S  = 132;                    // floats, pad 4 (epilogue reuses A region: 64*132*4 = 33792 B)

// ---------------------------------------------------------------------------
// Convert + transpose kernel.
// Blocks 0..255: transpose-convert 32x32 weight tiles into g_wT16 (n-major).
// Blocks 256..511: elementwise convert nodes -> g_nodes16.
// ---------------------------------------------------------------------------
__global__ void __launch_bounds__(256) cvt_kernel(
    const float* __restrict__ nodes,
    const float* __restrict__ Wq, const float* __restrict__ Wk,
    const float* __restrict__ Wv, const float* __restrict__ Wo)
{
    const int bx = blockIdx.x;
    const int tx = threadIdx.x;   // 0..31
    const int ty = threadIdx.y;   // 0..7
    if (bx < 256) {
        const int n0 = (bx & 31) * 32;
        const int k0 = (bx >> 5) * 32;
        __shared__ float s[32][33];
        const int mat  = n0 >> 8;
        const int col0 = n0 & 255;
        const float* W = (mat == 0) ? Wq : (mat == 1) ? Wk : (mat == 2) ? Wv : Wo;
#pragma unroll
        for (int j = 0; j < 4; j++) {
            const int k = k0 + ty + j * 8;
            s[ty + j * 8][tx] = W[k * 256 + col0 + tx];
        }
        __syncthreads();
#pragma unroll
        for (int j = 0; j < 4; j++) {
            const int n = n0 + ty + j * 8;
            g_wT16[n * 256 + k0 + tx] = __float2half(s[tx][ty + j * 8]);
        }
    } else {
        const int b   = bx - 256;
        const int tid = ty * 32 + tx;
#pragma unroll
        for (int r = 0; r < 2; r++) {
            const int i4 = b * 512 + r * 256 + tid;
            float4 v = ((const float4*)nodes)[i4];
            ((__half2*)g_nodes16)[i4 * 2 + 0] = __floats2half2_rn(v.x, v.y);
            ((__half2*)g_nodes16)[i4 * 2 + 1] = __floats2half2_rn(v.z, v.w);
        }
    }
}

// ---------------------------------------------------------------------------
// HMMA GEMM tile: C[m0:m0+64, 0:128] = A16[m0:m0+64, :] @ B16[wrow0:wrow0+128, :]^T + bias
// A16 row-major [*,256]; B rows are output-columns with K contiguous (col_major frag).
// 256 threads = 8 warps, warp grid 2x4, each warp 32x32 via 2x2 wmma fragments.
// ---------------------------------------------------------------------------
__device__ __forceinline__ void gemm_hmma_64x128(
    const __half* __restrict__ Asrc, int m0, int wrow0,
    float* __restrict__ C, const float* __restrict__ bias)
{
    extern __shared__ char smem[];
    __half* As = (__half*)smem;                 // [64][264]
    __half* Bs = (__half*)(smem + A_SM_B);      // [128][264]

    const int tid  = threadIdx.x;
    const int wid  = tid >> 5;
    const int wr   = wid >> 2;                  // 0..1  row tile
    const int wc   = wid & 3;                   // 0..3  col tile

    // ---- stage A (64x256) and B (128x256) in smem, vectorized ----
    {
        const uint4* Ag = (const uint4*)(Asrc + m0 * 256);
        const uint4* Bg = (const uint4*)(g_wT16 + wrow0 * 256);
#pragma unroll
        for (int i = tid; i < 2048; i += 256) {          // A: 64 rows x 32 chunks
            const int r = i >> 5, c = i & 31;
            *(uint4*)&As[r * LDA_S + c * 8] = Ag[r * 32 + c];
        }
#pragma unroll
        for (int i = tid; i < 4096; i += 256) {          // B: 128 rows x 32 chunks
            const int r = i >> 5, c = i & 31;
            *(uint4*)&Bs[r * LDA_S + c * 8] = Bg[r * 32 + c];
        }
    }
    __syncthreads();

    wmma::fragment<wmma::accumulator, 16, 16, 16, float> fc[2][2];
#pragma unroll
    for (int i = 0; i < 2; i++)
#pragma unroll
        for (int j = 0; j < 2; j++) wmma::fill_fragment(fc[i][j], 0.0f);

#pragma unroll
    for (int k0 = 0; k0 < 256; k0 += 16) {
        wmma::fragment<wmma::matrix_a, 16, 16, 16, __half, wmma::row_major> fa[2];
        wmma::fragment<wmma::matrix_b, 16, 16, 16, __half, wmma::col_major> fb[2];
#pragma unroll
        for (int i = 0; i < 2; i++)
            wmma::load_matrix_sync(fa[i], &As[(wr * 32 + i * 16) * LDA_S + k0], LDA_S);
#pragma unroll
        for (int j = 0; j < 2; j++)
            wmma::load_matrix_sync(fb[j], &Bs[(wc * 32 + j * 16) * LDA_S + k0], LDA_S);
#pragma unroll
        for (int i = 0; i < 2; i++)
#pragma unroll
            for (int j = 0; j < 2; j++)
                wmma::mma_sync(fc[i][j], fa[i], fb[j], fc[i][j]);
    }
    __syncthreads();   // done with As/Bs; reuse A region for the epilogue

    float* Cs = (float*)smem;                   // [64][132]
#pragma unroll
    for (int i = 0; i < 2; i++)
#pragma unroll
        for (int j = 0; j < 2; j++)
            wmma::store_matrix_sync(&Cs[(wr * 32 + i * 16) * LDC_S + wc * 32 + j * 16],
                                    fc[i][j], LDC_S, wmma::mem_row_major);
    __syncthreads();

    // ---- bias add + vectorized store: 64 rows x 32 float4 ----
#pragma unroll
    for (int i = tid; i < 2048; i += 256) {
        const int r = i >> 5, c4 = (i & 31) * 4;
        float4 v = *(float4*)&Cs[r * LDC_S + c4];
        v.x += bias[c4 + 0];
        v.y += bias[c4 + 1];
        v.z += bias[c4 + 2];
        v.w += bias[c4 + 3];
        *(float4*)&C[(m0 + r) * 256 + c4] = v;
    }
}

// ---------------------------------------------------------------------------
__global__ void __launch_bounds__(256) qkv_hmma_kernel(
    const float* __restrict__ bq, const float* __restrict__ bk,
    const float* __restrict__ bv)
{
    const int m0 = blockIdx.x * 64;
    const int nb = blockIdx.y * 128;        // 0..640
    const int which = nb >> 8;              // 0:q 1:k 2:v
    const int colin = nb & 255;             // 0 or 128
    float* C          = ((which == 0) ? g_q : (which == 1) ? g_k : g_v) + colin;
    const float* bias = ((which == 0) ? bq : (which == 1) ? bk : bv) + colin;
    gemm_hmma_64x128(g_nodes16, m0, nb, C, bias);
}

__global__ void __launch_bounds__(256) out_hmma_kernel(
    const float* __restrict__ bo, float* __restrict__ out)
{
    const int m0 = blockIdx.x * 64;
    const int nb = blockIdx.y * 128;        // 0 or 128
    gemm_hmma_64x128(g_attn16, m0, 768 + nb, out + nb, bo + nb);
}

// ---------------------------------------------------------------------------
// K2: per-(graph, head) attention with in-block edge bias (fp32 math,
// fp16 output for the HMMA out projection).
// ---------------------------------------------------------------------------
__global__ void __launch_bounds__(128) attn_kernel(
    const int* __restrict__ senders,
    const int* __restrict__ receivers,
    const float* __restrict__ edges,
    const float* __restrict__ We,
    const float* __restrict__ be)
{
    const int g = blockIdx.x >> 3;
    const int h = blockIdx.x & 7;
    const int tid = threadIdx.x;

    __shared__ float qs[64][33];
    __shared__ float ks[64][33];
    __shared__ float vs[64][33];
    __shared__ float sc[64][65];
    __shared__ float eb[EPG];

    for (int idx = tid; idx < 64 * 32; idx += 128) {
        const int r = idx >> 5;
        const int c = idx & 31;
        const int ga = (g * 64 + r) * 256 + h * 32 + c;
        qs[r][c] = g_q[ga];
        ks[r][c] = g_k[ga];
        vs[r][c] = g_v[ga];
    }

    for (int e = tid; e < EPG; e += 128) {
        const float* ef = &edges[(g * EPG + e) * EF];
        float s = be[h];
#pragma unroll
        for (int f = 0; f < EF; f++) s = fmaf(ef[f], We[f * NH + h], s);
        eb[e] = s;
    }
    __syncthreads();

    // scores 64x64, thread tile 4x8
    {
        const int i0 = (tid >> 3) * 4;
        const int j0 = (tid & 7) * 8;
        float acc[4][8];
#pragma unroll
        for (int i = 0; i < 4; i++)
#pragma unroll
            for (int j = 0; j < 8; j++) acc[i][j] = 0.f;

        for (int d = 0; d < 32; d++) {
            float a[4], b[8];
#pragma unroll
            for (int i = 0; i < 4; i++) a[i] = qs[i0 + i][d];
#pragma unroll
            for (int j = 0; j < 8; j++) b[j] = ks[j0 + j][d];
#pragma unroll
            for (int i = 0; i < 4; i++)
#pragma unroll
                for (int j = 0; j < 8; j++)
                    acc[i][j] = fmaf(a[i], b[j], acc[i][j]);
        }
#pragma unroll
        for (int i = 0; i < 4; i++)
#pragma unroll
            for (int j = 0; j < 8; j++)
                sc[i0 + i][j0 + j] = acc[i][j] * SCALE_F;
    }
    __syncthreads();

    // scatter edge bias (unique pairs -> no conflicts)
    for (int e = tid; e < EPG; e += 128) {
        const int ge = g * EPG + e;
        const int s  = senders[ge]   - g * 64;
        const int r  = receivers[ge] - g * 64;
        sc[r][s] += eb[e];
    }
    __syncthreads();

    // softmax over 64 keys, one warp per row
    {
        const int warp = tid >> 5;
        const int lane = tid & 31;
        for (int i = warp; i < 64; i += 4) {
            float x0 = sc[i][lane];
            float x1 = sc[i][lane + 32];
            float m = fmaxf(x0, x1);
#pragma unroll
            for (int o = 16; o > 0; o >>= 1)
                m = fmaxf(m, __shfl_xor_sync(0xffffffffu, m, o));
            float e0 = expf(x0 - m);
            float e1 = expf(x1 - m);
            float s = e0 + e1;
#pragma unroll
            for (int o = 16; o > 0; o >>= 1)
                s += __shfl_xor_sync(0xffffffffu, s, o);
            const float inv = 1.f / s;
            sc[i][lane]      = e0 * inv;
            sc[i][lane + 32] = e1 * inv;
        }
    }
    __syncthreads();

    // AV, thread tile 4x4 -> fp16 output
    {
        const int i0 = (tid >> 3) * 4;
        const int d0 = (tid & 7) * 4;
        float acc[4][4];
#pragma unroll
        for (int i = 0; i < 4; i++)
#pragma unroll
            for (int d = 0; d < 4; d++) acc[i][d] = 0.f;

        for (int j = 0; j < 64; j++) {
            float p[4], b[4];
#pragma unroll
            for (int i = 0; i < 4; i++) p[i] = sc[i0 + i][j];
#pragma unroll
            for (int d = 0; d < 4; d++) b[d] = vs[j][d0 + d];
#pragma unroll
            for (int i = 0; i < 4; i++)
#pragma unroll
                for (int d = 0; d < 4; d++)
                    acc[i][d] = fmaf(p[i], b[d], acc[i][d]);
        }
#pragma unroll
        for (int i = 0; i < 4; i++) {
            const int idx = (g * 64 + i0 + i) * 256 + h * 32 + d0;
            *(__half2*)&g_attn16[idx]     = __floats2half2_rn(acc[i][0], acc[i][1]);
            *(__half2*)&g_attn16[idx + 2] = __floats2half2_rn(acc[i][2], acc[i][3]);
        }
    }
}

// ---------------------------------------------------------------------------
extern "C" void kernel_launch(void* const* d_in, const int* in_sizes, int n_in,
                              void* d_out, int out_size)
{
    const float* nodes     = (const float*)d_in[0];
    const float* edges     = (const float*)d_in[1];
    const int*   senders   = (const int*)d_in[3];
    const int*   receivers = (const int*)d_in[4];
    const float* Wq = (const float*)d_in[5];
    const float* bq = (const float*)d_in[6];
    const float* Wk = (const float*)d_in[7];
    const float* bk = (const float*)d_in[8];
    const float* Wv = (const float*)d_in[9];
    const float* bv = (const float*)d_in[10];
    const float* Wo = (const float*)d_in[11];
    const float* bo = (const float*)d_in[12];
    const float* We = (const float*)d_in[13];
    const float* be = (const float*)d_in[14];
    float* out = (float*)d_out;

    static bool attr_done = false;
    if (!attr_done) {
        cudaFuncSetAttribute(qkv_hmma_kernel, cudaFuncAttributeMaxDynamicSharedMemorySize, SMEM_GEMM);
        cudaFuncSetAttribute(out_hmma_kernel, cudaFuncAttributeMaxDynamicSharedMemorySize, SMEM_GEMM);
        attr_done = true;
    }

    cvt_kernel<<<512, dim3(32, 8)>>>(nodes, Wq, Wk, Wv, Wo);
    qkv_hmma_kernel<<<dim3(32, 6), 256, SMEM_GEMM>>>(bq, bk, bv);
    attn_kernel<<<GG * NH, 128>>>(senders, receivers, edges, We, be);
    out_hmma_kernel<<<dim3(32, 2), 256, SMEM_GEMM>>>(bo, out);
}